// round 11
// baseline (speedup 1.0000x reference)
#include <cuda_runtime.h>
#include <cuda_fp16.h>
#include <cstdint>

#define SQ 2048
#define NB 4
#define NH 16
#define HD 64
#define DM 1024

// fp16 persistent tensors (allocation-guard-safe device globals)
__device__ __half g_xh[NB * SQ * DM];          // X in fp16
__device__ __half g_wh[3 * DM * DM];           // Wq|Wk|Wv in fp16
__device__ __half g_qh[NB * NH * SQ * HD];     // q (pre-scaled by log2e/8)
__device__ __half g_kh[NB * NH * SQ * HD];
__device__ __half g_vh[NB * NH * SQ * HD];

#define L2E 1.44269504f

// ---- mma.sync m16n8k16 fp16 ----
__device__ __forceinline__ void mma16816h(float* d, const uint32_t* a,
                                          uint32_t b0, uint32_t b1) {
    asm volatile(
        "mma.sync.aligned.m16n8k16.row.col.f32.f16.f16.f32 "
        "{%0,%1,%2,%3}, {%4,%5,%6,%7}, {%8,%9}, {%0,%1,%2,%3};"
        : "+f"(d[0]), "+f"(d[1]), "+f"(d[2]), "+f"(d[3])
        : "r"(a[0]), "r"(a[1]), "r"(a[2]), "r"(a[3]), "r"(b0), "r"(b1));
}
__device__ __forceinline__ uint32_t smem_u32(const void* p) {
    uint32_t a;
    asm("{ .reg .u64 t; cvta.to.shared.u64 t, %1; cvt.u32.u64 %0, t; }" : "=r"(a) : "l"(p));
    return a;
}
__device__ __forceinline__ void ldsm_x4(uint32_t& r0, uint32_t& r1, uint32_t& r2,
                                        uint32_t& r3, uint32_t addr) {
    asm volatile("ldmatrix.sync.aligned.m8n8.x4.shared.b16 {%0,%1,%2,%3}, [%4];"
                 : "=r"(r0), "=r"(r1), "=r"(r2), "=r"(r3) : "r"(addr));
}
__device__ __forceinline__ void ldsm_x4_t(uint32_t& r0, uint32_t& r1, uint32_t& r2,
                                          uint32_t& r3, uint32_t addr) {
    asm volatile("ldmatrix.sync.aligned.m8n8.x4.trans.shared.b16 {%0,%1,%2,%3}, [%4];"
                 : "=r"(r0), "=r"(r1), "=r"(r2), "=r"(r3) : "r"(addr));
}
__device__ __forceinline__ uint32_t h2bits(__half2 h) { return *(uint32_t*)&h; }

// ---- cp.async (sm_80 baseline; legal at compute_103) ----
#define CP16(sm, gp) asm volatile("cp.async.cg.shared.global [%0], [%1], 16;" \
                                  :: "r"(sm), "l"(gp))
#define CP_COMMIT()  asm volatile("cp.async.commit_group;" ::: "memory")
#define CP_WAIT2()   asm volatile("cp.async.wait_group 2;" ::: "memory")
#define CP_WAIT1()   asm volatile("cp.async.wait_group 1;" ::: "memory")
#define CP_WAIT0()   asm volatile("cp.async.wait_group 0;" ::: "memory")

// ============================================================================
// fp32 -> fp16 converts (one-time, memory-bound)
// ============================================================================
__global__ __launch_bounds__(256) void cvt_x(const float* __restrict__ src, int n)
{
    const int i = (blockIdx.x * 256 + threadIdx.x) * 8;
    if (i >= n) return;
    float4 a = *(const float4*)(src + i);
    float4 b = *(const float4*)(src + i + 4);
    *(uint4*)(g_xh + i) = make_uint4(
        h2bits(__floats2half2_rn(a.x, a.y)), h2bits(__floats2half2_rn(a.z, a.w)),
        h2bits(__floats2half2_rn(b.x, b.y)), h2bits(__floats2half2_rn(b.z, b.w)));
}
__global__ __launch_bounds__(256) void cvt_w(const float* __restrict__ Wq,
                                             const float* __restrict__ Wk,
                                             const float* __restrict__ Wv)
{
    const int i = (blockIdx.x * 256 + threadIdx.x) * 8;   // 0 .. 3*DM*DM
    const int which = i / (DM * DM);
    const int j = i - which * (DM * DM);
    const float* src = (which == 0) ? Wq : (which == 1) ? Wk : Wv;
    float4 a = *(const float4*)(src + j);
    float4 b = *(const float4*)(src + j + 4);
    *(uint4*)(g_wh + i) = make_uint4(
        h2bits(__floats2half2_rn(a.x, a.y)), h2bits(__floats2half2_rn(a.z, a.w)),
        h2bits(__floats2half2_rn(b.x, b.y)), h2bits(__floats2half2_rn(b.z, b.w)));
}

// ============================================================================
// QKV projection, fp16 in/out: dst = fp16((X @ W^T + b) * s).
// s = log2(e)/8 for q (exp2-domain softmax), 1 otherwise.
// CTA 128x128, KC=32, 4-stage cp.async ring, ONE barrier per chunk.
// ============================================================================
#define KCH 32
#define QST 4
#define QKV_SMEM (QST * 128 * 40 * 2 * 2)   // As + Bs, 81920 B

__global__ __launch_bounds__(256, 2) void qkv_gemm_f16(
    const float* __restrict__ bq, const float* __restrict__ bk,
    const float* __restrict__ bv)
{
    extern __shared__ __align__(16) char smraw[];
    __half (*As)[128][40] = (__half (*)[128][40])smraw;
    __half (*Bs)[128][40] = (__half (*)[128][40])(smraw + QST * 128 * 40 * 2);

    const int z = blockIdx.z;
    const float* bias = (z == 0) ? bq : (z == 1) ? bk : bv;
    __half* dst       = (z == 0) ? g_qh : (z == 1) ? g_kh : g_vh;
    const __half* Wp  = g_wh + (size_t)z * DM * DM;

    const int tid = threadIdx.x;
    const int wid = tid >> 5, lane = tid & 31;
    const int wm = wid & 3, wn = wid >> 2;
    const int m0 = blockIdx.y * 128, n0 = blockIdx.x * 128;

    const int lrow = tid >> 1;            // 0..127
    const int lck = (tid & 1) * 16;       // half-offset: 0 or 16
    const __half* Ag = g_xh + (size_t)(m0 + lrow) * DM + lck;
    const __half* Bg = Wp + (size_t)(n0 + lrow) * DM + lck;

    float acc[2][8][4];
    #pragma unroll
    for (int mt = 0; mt < 2; mt++)
        #pragma unroll
        for (int nt = 0; nt < 8; nt++)
            #pragma unroll
            for (int j = 0; j < 4; j++) acc[mt][nt][j] = 0.f;

    const int fr = lane >> 2, fc = (lane & 3) * 2;
    const int lrow16 = lane & 15;
    const int chalf = (lane & 16) >> 1;   // 0 or 8 halves

    const int NCH = DM / KCH;   // 32

    // prologue: stage chunks 0 and 1
    #pragma unroll
    for (int p = 0; p < 2; p++) {
        const __half* An = Ag + p * KCH;
        const __half* Bn = Bg + p * KCH;
        CP16(smem_u32(&As[p][lrow][lck]),     An);
        CP16(smem_u32(&As[p][lrow][lck + 8]), An + 8);
        CP16(smem_u32(&Bs[p][lrow][lck]),     Bn);
        CP16(smem_u32(&Bs[p][lrow][lck + 8]), Bn + 8);
        CP_COMMIT();
    }

    for (int c = 0; c < NCH; c++) {
        if (c + 2 < NCH) {
            const int st = (c + 2) & 3;
            const __half* An = Ag + (c + 2) * KCH;
            const __half* Bn = Bg + (c + 2) * KCH;
            CP16(smem_u32(&As[st][lrow][lck]),     An);
            CP16(smem_u32(&As[st][lrow][lck + 8]), An + 8);
            CP16(smem_u32(&Bs[st][lrow][lck]),     Bn);
            CP16(smem_u32(&Bs[st][lrow][lck + 8]), Bn + 8);
            CP_COMMIT();
            CP_WAIT2();
        } else if (c + 1 < NCH) {
            CP_WAIT1();
        } else {
            CP_WAIT0();
        }
        __syncthreads();   // single barrier: data visible + prev readers done
        const int b = c & 3;

        #pragma unroll
        for (int kk = 0; kk < KCH; kk += 16) {
            uint32_t a[2][4];
            #pragma unroll
            for (int mt = 0; mt < 2; mt++)
                ldsm_x4(a[mt][0], a[mt][1], a[mt][2], a[mt][3],
                        smem_u32(&As[b][wm * 32 + mt * 16 + lrow16][kk + chalf]));
            #pragma unroll
            for (int g = 0; g < 4; g++) {
                uint32_t r0, r1, r2, r3;
                ldsm_x4(r0, r1, r2, r3,
                        smem_u32(&Bs[b][wn * 64 + g * 16 + lrow16][kk + chalf]));
                mma16816h(acc[0][2 * g],     a[0], r0, r2);
                mma16816h(acc[1][2 * g],     a[1], r0, r2);
                mma16816h(acc[0][2 * g + 1], a[0], r1, r3);
                mma16816h(acc[1][2 * g + 1], a[1], r1, r3);
            }
        }
    }

    // ---- epilogue: +bias, (q: *log2e/8), fp16, into [B, H, S, 64] scratch ----
    const float s = (z == 0) ? 0.125f * L2E : 1.0f;
    #pragma unroll
    for (int mt = 0; mt < 2; mt++) {
        const int row0 = m0 + wm * 32 + mt * 16 + fr;
        const int b0r = row0 >> 11, s0 = row0 & (SQ - 1);
        const int row1 = row0 + 8;
        const int b1r = row1 >> 11, s1 = row1 & (SQ - 1);
        #pragma unroll
        for (int nt = 0; nt < 8; nt++) {
            const int col = n0 + wn * 64 + nt * 8 + fc;
            const int h = col >> 6, dd = col & 63;
            const float bz0 = bias[col], bz1 = bias[col + 1];
            __half* p0 = dst + ((size_t)(b0r * NH + h) * SQ + s0) * HD + dd;
            __half* p1 = dst + ((size_t)(b1r * NH + h) * SQ + s1) * HD + dd;
            *(__half2*)p0 = __floats2half2_rn((acc[mt][nt][0] + bz0) * s,
                                              (acc[mt][nt][1] + bz1) * s);
            *(__half2*)p1 = __floats2half2_rn((acc[mt][nt][2] + bz0) * s,
                                              (acc[mt][nt][3] + bz1) * s);
        }
    }
}

// ============================================================================
// Flash attention: fp16 scratch, 4-stage cp.async ring, one barrier/tile.
// exp2-domain softmax (scores pre-scaled by log2e via q).
// Row-sum l computed by the tensor pipe: extra MMA vs constant ones-fragment
// (l obeys the same rescale recurrence as any O column).
// ============================================================================
#define BQ 128
#define BK 64
#define VP 72
#define FST 4
#define FA_SMEM (FST * 2 * BK * VP * 2)   // 73728 B

__global__ __launch_bounds__(256, 2) void flash_attn_mma(
    const float* __restrict__ mask, float* __restrict__ out)
{
    extern __shared__ __align__(16) char smraw[];
    __half (*KVs)[2][BK][VP] = (__half (*)[2][BK][VP])smraw;

    const int tid = threadIdx.x;
    const int wid = tid >> 5, lane = tid & 31;
    const int fr = lane >> 2, fc = (lane & 3) * 2;
    const int bh = blockIdx.y;
    const int b = bh >> 4, h = bh & 15;
    const int q0 = blockIdx.x * BQ;
    const int qrow = q0 + wid * 16;

    const __half* Qg = g_qh + (size_t)bh * SQ * HD;
    const __half* Kg = g_kh + (size_t)bh * SQ * HD;
    const __half* Vg = g_vh + (size_t)bh * SQ * HD;
    const float* mrow = mask + (size_t)b * SQ;

    // ---- Q fragments: raw 32-bit loads from fp16 scratch (already scaled) ----
    uint32_t qf[4][4];
    #pragma unroll
    for (int kc = 0; kc < 4; kc++) {
        #pragma unroll
        for (int rr = 0; rr < 2; rr++) {
            const __half* p = Qg + (size_t)(qrow + fr + rr * 8) * HD + kc * 16 + fc;
            qf[kc][rr]     = *(const uint32_t*)p;
            qf[kc][rr + 2] = *(const uint32_t*)(p + 8);
        }
    }

    float accO[8][4];
    #pragma unroll
    for (int j = 0; j < 8; j++)
        #pragma unroll
        for (int i = 0; i < 4; i++) accO[j][i] = 0.f;
    float accL[4] = { 0.f, 0.f, 0.f, 0.f };   // l via ones-column MMA
    float m0r = -1e30f, m1r = -1e30f;
    const uint32_t ONE2 = 0x3C003C00u;        // half2(1.0, 1.0)

    // cp.async mapping: 64 rows x 64 halves; 4 threads/row x 2 x 8 halves
    const int krow = tid >> 2;
    const int kcol = (tid & 3) * 16;      // halves

    const int NIT = SQ / BK;   // 32

    // prologue: stage tiles 0 and 1
    #pragma unroll
    for (int p = 0; p < 2; p++) {
        const __half* kp = Kg + (size_t)(p * BK + krow) * HD + kcol;
        const __half* vp = Vg + (size_t)(p * BK + krow) * HD + kcol;
        CP16(smem_u32(&KVs[p][0][krow][kcol]),     kp);
        CP16(smem_u32(&KVs[p][0][krow][kcol + 8]), kp + 8);
        CP16(smem_u32(&KVs[p][1][krow][kcol]),     vp);
        CP16(smem_u32(&KVs[p][1][krow][kcol + 8]), vp + 8);
        CP_COMMIT();
    }

    const int lrow16 = lane & 15;
    const int chalf = (lane & 16) >> 1;

    for (int it = 0; it < NIT; it++) {
        if (it + 2 < NIT) {
            const int st = (it + 2) & 3;
            const __half* kp = Kg + (size_t)((it + 2) * BK + krow) * HD + kcol;
            const __half* vp = Vg + (size_t)((it + 2) * BK + krow) * HD + kcol;
            CP16(smem_u32(&KVs[st][0][krow][kcol]),     kp);
            CP16(smem_u32(&KVs[st][0][krow][kcol + 8]), kp + 8);
            CP16(smem_u32(&KVs[st][1][krow][kcol]),     vp);
            CP16(smem_u32(&KVs[st][1][krow][kcol + 8]), vp + 8);
            CP_COMMIT();
            CP_WAIT2();
        } else if (it + 1 < NIT) {
            CP_WAIT1();
        } else {
            CP_WAIT0();
        }
        __syncthreads();   // single barrier per tile
        const int bf = it & 3;
        const uint32_t kh_b = smem_u32(&KVs[bf][0][0][0]);
        const uint32_t vh_b = smem_u32(&KVs[bf][1][0][0]);
        const int j0 = it * BK;

        // ---- prefetch mask values (LDG hidden under the MMAs below) ----
        float2 mv[8];
        #pragma unroll
        for (int j = 0; j < 8; j++)
            mv[j] = *(const float2*)(mrow + j0 + j * 8 + fc);

        // ---- S = Q K^T (scores arrive in log2 domain) ----
        float sacc[8][4];
        #pragma unroll
        for (int j = 0; j < 8; j++)
            #pragma unroll
            for (int i = 0; i < 4; i++) sacc[j][i] = 0.f;

        #pragma unroll
        for (int kc = 0; kc < 4; kc++) {
            #pragma unroll
            for (int g = 0; g < 4; g++) {
                uint32_t r0, r1, r2, r3;
                uint32_t addr = kh_b +
                    ((g * 16 + lrow16) * VP + kc * 16 + chalf) * 2;
                ldsm_x4(r0, r1, r2, r3, addr);
                mma16816h(sacc[2 * g],     qf[kc], r0, r2);
                mma16816h(sacc[2 * g + 1], qf[kc], r1, r3);
            }
        }

        // ---- mask (log2-scaled) + online softmax in exp2 domain ----
        #pragma unroll
        for (int j = 0; j < 8; j++) {
            sacc[j][0] = fmaf(mv[j].x, L2E, sacc[j][0]);
            sacc[j][1] = fmaf(mv[j].y, L2E, sacc[j][1]);
            sacc[j][2] = fmaf(mv[j].x, L2E, sacc[j][2]);
            sacc[j][3] = fmaf(mv[j].y, L2E, sacc[j][3]);
        }
        float rmax0 = -1e30f, rmax1 = -1e30f;
        #pragma unroll
        for (int j = 0; j < 8; j++) {
            rmax0 = fmaxf(rmax0, fmaxf(sacc[j][0], sacc[j][1]));
            rmax1 = fmaxf(rmax1, fmaxf(sacc[j][2], sacc[j][3]));
        }
        rmax0 = fmaxf(rmax0, __shfl_xor_sync(0xffffffffu, rmax0, 1));
        rmax0 = fmaxf(rmax0, __shfl_xor_sync(0xffffffffu, rmax0, 2));
        rmax1 = fmaxf(rmax1, __shfl_xor_sync(0xffffffffu, rmax1, 1));
        rmax1 = fmaxf(rmax1, __shfl_xor_sync(0xffffffffu, rmax1, 2));

        const float mn0 = fmaxf(m0r, rmax0);
        const float mn1 = fmaxf(m1r, rmax1);
        const float a0 = exp2f(m0r - mn0);
        const float a1 = exp2f(m1r - mn1);
        m0r = mn0; m1r = mn1;

        uint32_t ph[16];
        #pragma unroll
        for (int j = 0; j < 8; j++) {
            float p0 = exp2f(sacc[j][0] - mn0);
            float p1 = exp2f(sacc[j][1] - mn0);
            float p2 = exp2f(sacc[j][2] - mn1);
            float p3 = exp2f(sacc[j][3] - mn1);
            ph[2 * j]     = h2bits(__floats2half2_rn(p0, p1));
            ph[2 * j + 1] = h2bits(__floats2half2_rn(p2, p3));
        }
        #pragma unroll
        for (int j = 0; j < 8; j++) {
            accO[j][0] *= a0; accO[j][1] *= a0;
            accO[j][2] *= a1; accO[j][3] *= a1;
        }
        accL[0] *= a0; accL[1] *= a0;
        accL[2] *= a1; accL[3] *= a1;

        // ---- O += P V, plus l += P @ ones (tensor-pipe row sums) ----
        #pragma unroll
        for (int kc = 0; kc < 4; kc++) {
            uint32_t pah[4] = { ph[4*kc], ph[4*kc+1], ph[4*kc+2], ph[4*kc+3] };
            mma16816h(accL, pah, ONE2, ONE2);
            #pragma unroll
            for (int dg = 0; dg < 4; dg++) {
                uint32_t off = vh_b + ((kc * 16 + lrow16) * VP + dg * 16 + chalf) * 2;
                uint32_t h0, h1, h2, h3;
                ldsm_x4_t(h0, h1, h2, h3, off);
                mma16816h(accO[2 * dg],     pah, h0, h1);
                mma16816h(accO[2 * dg + 1], pah, h2, h3);
            }
        }
    }

    // ---- epilogue: l is already complete per row (MMA summed over k) ----
    const float inv0 = 1.0f / accL[0], inv1 = 1.0f / accL[2];

    const int s0 = qrow + fr, s1 = s0 + 8;
    float* o0 = out + ((size_t)b * SQ + s0) * DM + h * HD;
    float* o1 = out + ((size_t)b * SQ + s1) * DM + h * HD;
    #pragma unroll
    for (int dt = 0; dt < 8; dt++) {
        const int d = dt * 8 + fc;
        *(float2*)(o0 + d) = make_float2(accO[dt][0] * inv0, accO[dt][1] * inv0);
        *(float2*)(o1 + d) = make_float2(accO[dt][2] * inv1, accO[dt][3] * inv1);
    }
}

extern "C" void kernel_launch(void* const* d_in, const int* in_sizes, int n_in,
                              void* d_out, int out_size)
{
    const float* X   = (const float*)d_in[0];
    const float* Mk  = (const float*)d_in[1];
    const float* Wq  = (const float*)d_in[2];
    const float* bq  = (const float*)d_in[3];
    const float* Wk  = (const float*)d_in[4];
    const float* bk  = (const float*)d_in[5];
    const float* Wv  = (const float*)d_in[6];
    const float* bv  = (const float*)d_in[7];
    float* out = (float*)d_out;

    cudaFuncSetAttribute(qkv_gemm_f16,
                         cudaFuncAttributeMaxDynamicSharedMemorySize, QKV_SMEM);
    cudaFuncSetAttribute(flash_attn_mma,
                         cudaFuncAttributeMaxDynamicSharedMemorySize, FA_SMEM);

    cvt_x<<<NB * SQ * DM / 2048, 256>>>(X, NB * SQ * DM);
    cvt_w<<<3 * DM * DM / 2048, 256>>>(Wq, Wk, Wv);
    qkv_gemm_f16<<<dim3(8, 64, 3), 256, QKV_SMEM>>>(bq, bk, bv);
    flash_attn_mma<<<dim3(SQ / BQ, NB * NH), 256, FA_SMEM>>>(Mk, out);
}

// round 12
// speedup vs baseline: 1.5345x; 1.5345x over previous
#include <cuda_runtime.h>
#include <cuda_fp16.h>
#include <cstdint>

#define SQ 2048
#define NB 4
#define NH 16
#define HD 64
#define DM 1024

// fp16 persistent tensors (allocation-guard-safe device globals)
__device__ __half g_xh[NB * SQ * DM];          // X in fp16
__device__ __half g_wh[3 * DM * DM];           // Wq|Wk|Wv in fp16
__device__ __half g_qh[NB * NH * SQ * HD];     // q (pre-scaled by log2e/8)
__device__ __half g_kh[NB * NH * SQ * HD];
__device__ __half g_vh[NB * NH * SQ * HD];

#define L2E 1.44269504f

// ---- mma.sync m16n8k16 fp16 ----
__device__ __forceinline__ void mma16816h(float* d, const uint32_t* a,
                                          uint32_t b0, uint32_t b1) {
    asm volatile(
        "mma.sync.aligned.m16n8k16.row.col.f32.f16.f16.f32 "
        "{%0,%1,%2,%3}, {%4,%5,%6,%7}, {%8,%9}, {%0,%1,%2,%3};"
        : "+f"(d[0]), "+f"(d[1]), "+f"(d[2]), "+f"(d[3])
        : "r"(a[0]), "r"(a[1]), "r"(a[2]), "r"(a[3]), "r"(b0), "r"(b1));
}
__device__ __forceinline__ uint32_t smem_u32(const void* p) {
    uint32_t a;
    asm("{ .reg .u64 t; cvta.to.shared.u64 t, %1; cvt.u32.u64 %0, t; }" : "=r"(a) : "l"(p));
    return a;
}
__device__ __forceinline__ void ldsm_x4(uint32_t& r0, uint32_t& r1, uint32_t& r2,
                                        uint32_t& r3, uint32_t addr) {
    asm volatile("ldmatrix.sync.aligned.m8n8.x4.shared.b16 {%0,%1,%2,%3}, [%4];"
                 : "=r"(r0), "=r"(r1), "=r"(r2), "=r"(r3) : "r"(addr));
}
__device__ __forceinline__ void ldsm_x4_t(uint32_t& r0, uint32_t& r1, uint32_t& r2,
                                          uint32_t& r3, uint32_t addr) {
    asm volatile("ldmatrix.sync.aligned.m8n8.x4.trans.shared.b16 {%0,%1,%2,%3}, [%4];"
                 : "=r"(r0), "=r"(r1), "=r"(r2), "=r"(r3) : "r"(addr));
}
__device__ __forceinline__ uint32_t h2bits(__half2 h) { return *(uint32_t*)&h; }

// ---- guaranteed-MUFU exp2 (exp2f is a slow libdevice routine w/o fast-math) ----
__device__ __forceinline__ float ex2(float x) {
    float r; asm("ex2.approx.f32 %0, %1;" : "=f"(r) : "f"(x)); return r;
}

// ---- cp.async (sm_80 baseline; legal at compute_103) ----
#define CP16(sm, gp) asm volatile("cp.async.cg.shared.global [%0], [%1], 16;" \
                                  :: "r"(sm), "l"(gp))
#define CP_COMMIT()  asm volatile("cp.async.commit_group;" ::: "memory")
#define CP_WAIT2()   asm volatile("cp.async.wait_group 2;" ::: "memory")
#define CP_WAIT1()   asm volatile("cp.async.wait_group 1;" ::: "memory")
#define CP_WAIT0()   asm volatile("cp.async.wait_group 0;" ::: "memory")

// ============================================================================
// fp32 -> fp16 converts (one-time, memory-bound)
// ============================================================================
__global__ __launch_bounds__(256) void cvt_x(const float* __restrict__ src, int n)
{
    const int i = (blockIdx.x * 256 + threadIdx.x) * 8;
    if (i >= n) return;
    float4 a = *(const float4*)(src + i);
    float4 b = *(const float4*)(src + i + 4);
    *(uint4*)(g_xh + i) = make_uint4(
        h2bits(__floats2half2_rn(a.x, a.y)), h2bits(__floats2half2_rn(a.z, a.w)),
        h2bits(__floats2half2_rn(b.x, b.y)), h2bits(__floats2half2_rn(b.z, b.w)));
}
__global__ __launch_bounds__(256) void cvt_w(const float* __restrict__ Wq,
                                             const float* __restrict__ Wk,
                                             const float* __restrict__ Wv)
{
    const int i = (blockIdx.x * 256 + threadIdx.x) * 8;   // 0 .. 3*DM*DM
    const int which = i / (DM * DM);
    const int j = i - which * (DM * DM);
    const float* src = (which == 0) ? Wq : (which == 1) ? Wk : Wv;
    float4 a = *(const float4*)(src + j);
    float4 b = *(const float4*)(src + j + 4);
    *(uint4*)(g_wh + i) = make_uint4(
        h2bits(__floats2half2_rn(a.x, a.y)), h2bits(__floats2half2_rn(a.z, a.w)),
        h2bits(__floats2half2_rn(b.x, b.y)), h2bits(__floats2half2_rn(b.z, b.w)));
}

// ============================================================================
// QKV projection, fp16 in/out: dst = fp16((X @ W^T + b) * s).
// s = log2(e)/8 for q (exp2-domain softmax), 1 otherwise.
// CTA 128x128, KC=32, 4-stage cp.async ring, ONE barrier per chunk.
// ============================================================================
#define KCH 32
#define QST 4
#define QKV_SMEM (QST * 128 * 40 * 2 * 2)   // As + Bs, 81920 B

__global__ __launch_bounds__(256, 2) void qkv_gemm_f16(
    const float* __restrict__ bq, const float* __restrict__ bk,
    const float* __restrict__ bv)
{
    extern __shared__ __align__(16) char smraw[];
    __half (*As)[128][40] = (__half (*)[128][40])smraw;
    __half (*Bs)[128][40] = (__half (*)[128][40])(smraw + QST * 128 * 40 * 2);

    const int z = blockIdx.z;
    const float* bias = (z == 0) ? bq : (z == 1) ? bk : bv;
    __half* dst       = (z == 0) ? g_qh : (z == 1) ? g_kh : g_vh;
    const __half* Wp  = g_wh + (size_t)z * DM * DM;

    const int tid = threadIdx.x;
    const int wid = tid >> 5, lane = tid & 31;
    const int wm = wid & 3, wn = wid >> 2;
    const int m0 = blockIdx.y * 128, n0 = blockIdx.x * 128;

    const int lrow = tid >> 1;            // 0..127
    const int lck = (tid & 1) * 16;       // half-offset: 0 or 16
    const __half* Ag = g_xh + (size_t)(m0 + lrow) * DM + lck;
    const __half* Bg = Wp + (size_t)(n0 + lrow) * DM + lck;

    float acc[2][8][4];
    #pragma unroll
    for (int mt = 0; mt < 2; mt++)
        #pragma unroll
        for (int nt = 0; nt < 8; nt++)
            #pragma unroll
            for (int j = 0; j < 4; j++) acc[mt][nt][j] = 0.f;

    const int fr = lane >> 2, fc = (lane & 3) * 2;
    const int lrow16 = lane & 15;
    const int chalf = (lane & 16) >> 1;   // 0 or 8 halves

    const int NCH = DM / KCH;   // 32

    // prologue: stage chunks 0 and 1
    #pragma unroll
    for (int p = 0; p < 2; p++) {
        const __half* An = Ag + p * KCH;
        const __half* Bn = Bg + p * KCH;
        CP16(smem_u32(&As[p][lrow][lck]),     An);
        CP16(smem_u32(&As[p][lrow][lck + 8]), An + 8);
        CP16(smem_u32(&Bs[p][lrow][lck]),     Bn);
        CP16(smem_u32(&Bs[p][lrow][lck + 8]), Bn + 8);
        CP_COMMIT();
    }

    for (int c = 0; c < NCH; c++) {
        if (c + 2 < NCH) {
            const int st = (c + 2) & 3;
            const __half* An = Ag + (c + 2) * KCH;
            const __half* Bn = Bg + (c + 2) * KCH;
            CP16(smem_u32(&As[st][lrow][lck]),     An);
            CP16(smem_u32(&As[st][lrow][lck + 8]), An + 8);
            CP16(smem_u32(&Bs[st][lrow][lck]),     Bn);
            CP16(smem_u32(&Bs[st][lrow][lck + 8]), Bn + 8);
            CP_COMMIT();
            CP_WAIT2();
        } else if (c + 1 < NCH) {
            CP_WAIT1();
        } else {
            CP_WAIT0();
        }
        __syncthreads();   // single barrier: data visible + prev readers done
        const int b = c & 3;

        #pragma unroll
        for (int kk = 0; kk < KCH; kk += 16) {
            uint32_t a[2][4];
            #pragma unroll
            for (int mt = 0; mt < 2; mt++)
                ldsm_x4(a[mt][0], a[mt][1], a[mt][2], a[mt][3],
                        smem_u32(&As[b][wm * 32 + mt * 16 + lrow16][kk + chalf]));
            #pragma unroll
            for (int g = 0; g < 4; g++) {
                uint32_t r0, r1, r2, r3;
                ldsm_x4(r0, r1, r2, r3,
                        smem_u32(&Bs[b][wn * 64 + g * 16 + lrow16][kk + chalf]));
                mma16816h(acc[0][2 * g],     a[0], r0, r2);
                mma16816h(acc[1][2 * g],     a[1], r0, r2);
                mma16816h(acc[0][2 * g + 1], a[0], r1, r3);
                mma16816h(acc[1][2 * g + 1], a[1], r1, r3);
            }
        }
    }

    // ---- epilogue: +bias, (q: *log2e/8), fp16, into [B, H, S, 64] scratch ----
    const float s = (z == 0) ? 0.125f * L2E : 1.0f;
    #pragma unroll
    for (int mt = 0; mt < 2; mt++) {
        const int row0 = m0 + wm * 32 + mt * 16 + fr;
        const int b0r = row0 >> 11, s0 = row0 & (SQ - 1);
        const int row1 = row0 + 8;
        const int b1r = row1 >> 11, s1 = row1 & (SQ - 1);
        #pragma unroll
        for (int nt = 0; nt < 8; nt++) {
            const int col = n0 + wn * 64 + nt * 8 + fc;
            const int h = col >> 6, dd = col & 63;
            const float bz0 = bias[col], bz1 = bias[col + 1];
            __half* p0 = dst + ((size_t)(b0r * NH + h) * SQ + s0) * HD + dd;
            __half* p1 = dst + ((size_t)(b1r * NH + h) * SQ + s1) * HD + dd;
            *(__half2*)p0 = __floats2half2_rn((acc[mt][nt][0] + bz0) * s,
                                              (acc[mt][nt][1] + bz1) * s);
            *(__half2*)p1 = __floats2half2_rn((acc[mt][nt][2] + bz0) * s,
                                              (acc[mt][nt][3] + bz1) * s);
        }
    }
}

// ============================================================================
// Flash attention: fp16 scratch, 4-stage cp.async ring, one barrier/tile.
// exp2-domain softmax via explicit ex2.approx (MUFU), scores pre-scaled by
// log2e through q. Row-sum l on the tensor pipe (ones-column MMA).
// ============================================================================
#define BQ 128
#define BK 64
#define VP 72
#define FST 4
#define FA_SMEM (FST * 2 * BK * VP * 2)   // 73728 B

__global__ __launch_bounds__(256, 2) void flash_attn_mma(
    const float* __restrict__ mask, float* __restrict__ out)
{
    extern __shared__ __align__(16) char smraw[];
    __half (*KVs)[2][BK][VP] = (__half (*)[2][BK][VP])smraw;

    const int tid = threadIdx.x;
    const int wid = tid >> 5, lane = tid & 31;
    const int fr = lane >> 2, fc = (lane & 3) * 2;
    const int bh = blockIdx.y;
    const int b = bh >> 4, h = bh & 15;
    const int q0 = blockIdx.x * BQ;
    const int qrow = q0 + wid * 16;

    const __half* Qg = g_qh + (size_t)bh * SQ * HD;
    const __half* Kg = g_kh + (size_t)bh * SQ * HD;
    const __half* Vg = g_vh + (size_t)bh * SQ * HD;
    const float* mrow = mask + (size_t)b * SQ;

    // ---- Q fragments: raw 32-bit loads from fp16 scratch (already scaled) ----
    uint32_t qf[4][4];
    #pragma unroll
    for (int kc = 0; kc < 4; kc++) {
        #pragma unroll
        for (int rr = 0; rr < 2; rr++) {
            const __half* p = Qg + (size_t)(qrow + fr + rr * 8) * HD + kc * 16 + fc;
            qf[kc][rr]     = *(const uint32_t*)p;
            qf[kc][rr + 2] = *(const uint32_t*)(p + 8);
        }
    }

    float accO[8][4];
    #pragma unroll
    for (int j = 0; j < 8; j++)
        #pragma unroll
        for (int i = 0; i < 4; i++) accO[j][i] = 0.f;
    float accL[4] = { 0.f, 0.f, 0.f, 0.f };   // l via ones-column MMA
    float m0r = -1e30f, m1r = -1e30f;
    const uint32_t ONE2 = 0x3C003C00u;        // half2(1.0, 1.0)

    // cp.async mapping: 64 rows x 64 halves; 4 threads/row x 2 x 8 halves
    const int krow = tid >> 2;
    const int kcol = (tid & 3) * 16;      // halves

    const int NIT = SQ / BK;   // 32

    // prologue: stage tiles 0 and 1
    #pragma unroll
    for (int p = 0; p < 2; p++) {
        const __half* kp = Kg + (size_t)(p * BK + krow) * HD + kcol;
        const __half* vp = Vg + (size_t)(p * BK + krow) * HD + kcol;
        CP16(smem_u32(&KVs[p][0][krow][kcol]),     kp);
        CP16(smem_u32(&KVs[p][0][krow][kcol + 8]), kp + 8);
        CP16(smem_u32(&KVs[p][1][krow][kcol]),     vp);
        CP16(smem_u32(&KVs[p][1][krow][kcol + 8]), vp + 8);
        CP_COMMIT();
    }

    const int lrow16 = lane & 15;
    const int chalf = (lane & 16) >> 1;

    for (int it = 0; it < NIT; it++) {
        if (it + 2 < NIT) {
            const int st = (it + 2) & 3;
            const __half* kp = Kg + (size_t)((it + 2) * BK + krow) * HD + kcol;
            const __half* vp = Vg + (size_t)((it + 2) * BK + krow) * HD + kcol;
            CP16(smem_u32(&KVs[st][0][krow][kcol]),     kp);
            CP16(smem_u32(&KVs[st][0][krow][kcol + 8]), kp + 8);
            CP16(smem_u32(&KVs[st][1][krow][kcol]),     vp);
            CP16(smem_u32(&KVs[st][1][krow][kcol + 8]), vp + 8);
            CP_COMMIT();
            CP_WAIT2();
        } else if (it + 1 < NIT) {
            CP_WAIT1();
        } else {
            CP_WAIT0();
        }
        __syncthreads();   // single barrier per tile
        const int bf = it & 3;
        const uint32_t kh_b = smem_u32(&KVs[bf][0][0][0]);
        const uint32_t vh_b = smem_u32(&KVs[bf][1][0][0]);
        const int j0 = it * BK;

        // ---- prefetch mask values (LDG hidden under the MMAs below) ----
        float2 mv[8];
        #pragma unroll
        for (int j = 0; j < 8; j++)
            mv[j] = *(const float2*)(mrow + j0 + j * 8 + fc);

        // ---- S = Q K^T (scores arrive in log2 domain) ----
        float sacc[8][4];
        #pragma unroll
        for (int j = 0; j < 8; j++)
            #pragma unroll
            for (int i = 0; i < 4; i++) sacc[j][i] = 0.f;

        #pragma unroll
        for (int kc = 0; kc < 4; kc++) {
            #pragma unroll
            for (int g = 0; g < 4; g++) {
                uint32_t r0, r1, r2, r3;
                uint32_t addr = kh_b +
                    ((g * 16 + lrow16) * VP + kc * 16 + chalf) * 2;
                ldsm_x4(r0, r1, r2, r3, addr);
                mma16816h(sacc[2 * g],     qf[kc], r0, r2);
                mma16816h(sacc[2 * g + 1], qf[kc], r1, r3);
            }
        }

        // ---- mask (log2-scaled) + online softmax in exp2 domain ----
        #pragma unroll
        for (int j = 0; j < 8; j++) {
            sacc[j][0] = fmaf(mv[j].x, L2E, sacc[j][0]);
            sacc[j][1] = fmaf(mv[j].y, L2E, sacc[j][1]);
            sacc[j][2] = fmaf(mv[j].x, L2E, sacc[j][2]);
            sacc[j][3] = fmaf(mv[j].y, L2E, sacc[j][3]);
        }
        float rmax0 = -1e30f, rmax1 = -1e30f;
        #pragma unroll
        for (int j = 0; j < 8; j++) {
            rmax0 = fmaxf(rmax0, fmaxf(sacc[j][0], sacc[j][1]));
            rmax1 = fmaxf(rmax1, fmaxf(sacc[j][2], sacc[j][3]));
        }
        rmax0 = fmaxf(rmax0, __shfl_xor_sync(0xffffffffu, rmax0, 1));
        rmax0 = fmaxf(rmax0, __shfl_xor_sync(0xffffffffu, rmax0, 2));
        rmax1 = fmaxf(rmax1, __shfl_xor_sync(0xffffffffu, rmax1, 1));
        rmax1 = fmaxf(rmax1, __shfl_xor_sync(0xffffffffu, rmax1, 2));

        const float mn0 = fmaxf(m0r, rmax0);
        const float mn1 = fmaxf(m1r, rmax1);
        const float a0 = ex2(m0r - mn0);
        const float a1 = ex2(m1r - mn1);
        m0r = mn0; m1r = mn1;

        uint32_t ph[16];
        #pragma unroll
        for (int j = 0; j < 8; j++) {
            float p0 = ex2(sacc[j][0] - mn0);
            float p1 = ex2(sacc[j][1] - mn0);
            float p2 = ex2(sacc[j][2] - mn1);
            float p3 = ex2(sacc[j][3] - mn1);
            ph[2 * j]     = h2bits(__floats2half2_rn(p0, p1));
            ph[2 * j + 1] = h2bits(__floats2half2_rn(p2, p3));
        }
        #pragma unroll
        for (int j = 0; j < 8; j++) {
            accO[j][0] *= a0; accO[j][1] *= a0;
            accO[j][2] *= a1; accO[j][3] *= a1;
        }
        accL[0] *= a0; accL[1] *= a0;
        accL[2] *= a1; accL[3] *= a1;

        // ---- O += P V, plus l += P @ ones (tensor-pipe row sums) ----
        #pragma unroll
        for (int kc = 0; kc < 4; kc++) {
            uint32_t pah[4] = { ph[4*kc], ph[4*kc+1], ph[4*kc+2], ph[4*kc+3] };
            mma16816h(accL, pah, ONE2, ONE2);
            #pragma unroll
            for (int dg = 0; dg < 4; dg++) {
                uint32_t off = vh_b + ((kc * 16 + lrow16) * VP + dg * 16 + chalf) * 2;
                uint32_t h0, h1, h2, h3;
                ldsm_x4_t(h0, h1, h2, h3, off);
                mma16816h(accO[2 * dg],     pah, h0, h1);
                mma16816h(accO[2 * dg + 1], pah, h2, h3);
            }
        }
    }

    // ---- epilogue: l is already complete per row (MMA summed over k) ----
    const float inv0 = 1.0f / accL[0], inv1 = 1.0f / accL[2];

    const int s0 = qrow + fr, s1 = s0 + 8;
    float* o0 = out + ((size_t)b * SQ + s0) * DM + h * HD;
    float* o1 = out + ((size_t)b * SQ + s1) * DM + h * HD;
    #pragma unroll
    for (int dt = 0; dt < 8; dt++) {
        const int d = dt * 8 + fc;
        *(float2*)(o0 + d) = make_float2(accO[dt][0] * inv0, accO[dt][1] * inv0);
        *(float2*)(o1 + d) = make_float2(accO[dt][2] * inv1, accO[dt][3] * inv1);
    }
}

extern "C" void kernel_launch(void* const* d_in, const int* in_sizes, int n_in,
                              void* d_out, int out_size)
{
    const float* X   = (const float*)d_in[0];
    const float* Mk  = (const float*)d_in[1];
    const float* Wq  = (const float*)d_in[2];
    const float* bq  = (const float*)d_in[3];
    const float* Wk  = (const float*)d_in[4];
    const float* bk  = (const float*)d_in[5];
    const float* Wv  = (const float*)d_in[6];
    const float* bv  = (const float*)d_in[7];
    float* out = (float*)d_out;

    cudaFuncSetAttribute(qkv_gemm_f16,
                         cudaFuncAttributeMaxDynamicSharedMemorySize, QKV_SMEM);
    cudaFuncSetAttribute(flash_attn_mma,
                         cudaFuncAttributeMaxDynamicSharedMemorySize, FA_SMEM);

    cvt_x<<<NB * SQ * DM / 2048, 256>>>(X, NB * SQ * DM);
    cvt_w<<<3 * DM * DM / 2048, 256>>>(Wq, Wk, Wv);
    qkv_gemm_f16<<<dim3(8, 64, 3), 256, QKV_SMEM>>>(bq, bk, bv);
    flash_attn_mma<<<dim3(SQ / BQ, NB * NH), 256, FA_SMEM>>>(Mk, out);
}

// round 13
// speedup vs baseline: 1.5560x; 1.0140x over previous
#include <cuda_runtime.h>
#include <cuda_fp16.h>
#include <cstdint>

#define SQ 2048
#define NB 4
#define NH 16
#define HD 64
#define DM 1024

// fp16 persistent tensors (allocation-guard-safe device globals)
__device__ __half g_xh[NB * SQ * DM];          // X in fp16
__device__ __half g_wh[3 * DM * DM];           // Wq|Wk|Wv in fp16
__device__ __half g_qh[NB * NH * SQ * HD];     // q (pre-scaled by log2e/8)
__device__ __half g_kh[NB * NH * SQ * HD];
__device__ __half g_vh[NB * NH * SQ * HD];

#define L2E 1.44269504f

// ---- mma.sync m16n8k16 fp16 ----
__device__ __forceinline__ void mma16816h(float* d, const uint32_t* a,
                                          uint32_t b0, uint32_t b1) {
    asm volatile(
        "mma.sync.aligned.m16n8k16.row.col.f32.f16.f16.f32 "
        "{%0,%1,%2,%3}, {%4,%5,%6,%7}, {%8,%9}, {%0,%1,%2,%3};"
        : "+f"(d[0]), "+f"(d[1]), "+f"(d[2]), "+f"(d[3])
        : "r"(a[0]), "r"(a[1]), "r"(a[2]), "r"(a[3]), "r"(b0), "r"(b1));
}
__device__ __forceinline__ uint32_t smem_u32(const void* p) {
    uint32_t a;
    asm("{ .reg .u64 t; cvta.to.shared.u64 t, %1; cvt.u32.u64 %0, t; }" : "=r"(a) : "l"(p));
    return a;
}
__device__ __forceinline__ void ldsm_x4(uint32_t& r0, uint32_t& r1, uint32_t& r2,
                                        uint32_t& r3, uint32_t addr) {
    asm volatile("ldmatrix.sync.aligned.m8n8.x4.shared.b16 {%0,%1,%2,%3}, [%4];"
                 : "=r"(r0), "=r"(r1), "=r"(r2), "=r"(r3) : "r"(addr));
}
__device__ __forceinline__ void ldsm_x4_t(uint32_t& r0, uint32_t& r1, uint32_t& r2,
                                          uint32_t& r3, uint32_t addr) {
    asm volatile("ldmatrix.sync.aligned.m8n8.x4.trans.shared.b16 {%0,%1,%2,%3}, [%4];"
                 : "=r"(r0), "=r"(r1), "=r"(r2), "=r"(r3) : "r"(addr));
}
__device__ __forceinline__ uint32_t h2bits(__half2 h) { return *(uint32_t*)&h; }

// ---- guaranteed-MUFU exp2 (exp2f is a slow libdevice routine w/o fast-math) ----
__device__ __forceinline__ float ex2(float x) {
    float r; asm("ex2.approx.f32 %0, %1;" : "=f"(r) : "f"(x)); return r;
}
// packed half2 exp2: one MUFU op for two exponentials, result is the P fragment
__device__ __forceinline__ uint32_t ex2h2(uint32_t x) {
    uint32_t r; asm("ex2.approx.f16x2 %0, %1;" : "=r"(r) : "r"(x)); return r;
}

// ---- cp.async (sm_80 baseline; legal at compute_103) ----
#define CP16(sm, gp) asm volatile("cp.async.cg.shared.global [%0], [%1], 16;" \
                                  :: "r"(sm), "l"(gp))
#define CP_COMMIT()  asm volatile("cp.async.commit_group;" ::: "memory")
#define CP_WAIT2()   asm volatile("cp.async.wait_group 2;" ::: "memory")
#define CP_WAIT1()   asm volatile("cp.async.wait_group 1;" ::: "memory")
#define CP_WAIT0()   asm volatile("cp.async.wait_group 0;" ::: "memory")

// ============================================================================
// fp32 -> fp16 converts (one-time, memory-bound)
// ============================================================================
__global__ __launch_bounds__(256) void cvt_x(const float* __restrict__ src, int n)
{
    const int i = (blockIdx.x * 256 + threadIdx.x) * 8;
    if (i >= n) return;
    float4 a = *(const float4*)(src + i);
    float4 b = *(const float4*)(src + i + 4);
    *(uint4*)(g_xh + i) = make_uint4(
        h2bits(__floats2half2_rn(a.x, a.y)), h2bits(__floats2half2_rn(a.z, a.w)),
        h2bits(__floats2half2_rn(b.x, b.y)), h2bits(__floats2half2_rn(b.z, b.w)));
}
__global__ __launch_bounds__(256) void cvt_w(const float* __restrict__ Wq,
                                             const float* __restrict__ Wk,
                                             const float* __restrict__ Wv)
{
    const int i = (blockIdx.x * 256 + threadIdx.x) * 8;   // 0 .. 3*DM*DM
    const int which = i / (DM * DM);
    const int j = i - which * (DM * DM);
    const float* src = (which == 0) ? Wq : (which == 1) ? Wk : Wv;
    float4 a = *(const float4*)(src + j);
    float4 b = *(const float4*)(src + j + 4);
    *(uint4*)(g_wh + i) = make_uint4(
        h2bits(__floats2half2_rn(a.x, a.y)), h2bits(__floats2half2_rn(a.z, a.w)),
        h2bits(__floats2half2_rn(b.x, b.y)), h2bits(__floats2half2_rn(b.z, b.w)));
}

// ============================================================================
// QKV projection, fp16 in/out: dst = fp16((X @ W^T + b) * s).
// s = log2(e)/8 for q (exp2-domain softmax), 1 otherwise.
// CTA 128x128, KC=32, 4-stage cp.async ring, ONE barrier per chunk.
// ============================================================================
#define KCH 32
#define QST 4
#define QKV_SMEM (QST * 128 * 40 * 2 * 2)   // As + Bs, 81920 B

__global__ __launch_bounds__(256, 2) void qkv_gemm_f16(
    const float* __restrict__ bq, const float* __restrict__ bk,
    const float* __restrict__ bv)
{
    extern __shared__ __align__(16) char smraw[];
    __half (*As)[128][40] = (__half (*)[128][40])smraw;
    __half (*Bs)[128][40] = (__half (*)[128][40])(smraw + QST * 128 * 40 * 2);

    const int z = blockIdx.z;
    const float* bias = (z == 0) ? bq : (z == 1) ? bk : bv;
    __half* dst       = (z == 0) ? g_qh : (z == 1) ? g_kh : g_vh;
    const __half* Wp  = g_wh + (size_t)z * DM * DM;

    const int tid = threadIdx.x;
    const int wid = tid >> 5, lane = tid & 31;
    const int wm = wid & 3, wn = wid >> 2;
    const int m0 = blockIdx.y * 128, n0 = blockIdx.x * 128;

    const int lrow = tid >> 1;            // 0..127
    const int lck = (tid & 1) * 16;       // half-offset: 0 or 16
    const __half* Ag = g_xh + (size_t)(m0 + lrow) * DM + lck;
    const __half* Bg = Wp + (size_t)(n0 + lrow) * DM + lck;

    float acc[2][8][4];
    #pragma unroll
    for (int mt = 0; mt < 2; mt++)
        #pragma unroll
        for (int nt = 0; nt < 8; nt++)
            #pragma unroll
            for (int j = 0; j < 4; j++) acc[mt][nt][j] = 0.f;

    const int fr = lane >> 2, fc = (lane & 3) * 2;
    const int lrow16 = lane & 15;
    const int chalf = (lane & 16) >> 1;   // 0 or 8 halves

    const int NCH = DM / KCH;   // 32

    // prologue: stage chunks 0 and 1
    #pragma unroll
    for (int p = 0; p < 2; p++) {
        const __half* An = Ag + p * KCH;
        const __half* Bn = Bg + p * KCH;
        CP16(smem_u32(&As[p][lrow][lck]),     An);
        CP16(smem_u32(&As[p][lrow][lck + 8]), An + 8);
        CP16(smem_u32(&Bs[p][lrow][lck]),     Bn);
        CP16(smem_u32(&Bs[p][lrow][lck + 8]), Bn + 8);
        CP_COMMIT();
    }

    for (int c = 0; c < NCH; c++) {
        if (c + 2 < NCH) {
            const int st = (c + 2) & 3;
            const __half* An = Ag + (c + 2) * KCH;
            const __half* Bn = Bg + (c + 2) * KCH;
            CP16(smem_u32(&As[st][lrow][lck]),     An);
            CP16(smem_u32(&As[st][lrow][lck + 8]), An + 8);
            CP16(smem_u32(&Bs[st][lrow][lck]),     Bn);
            CP16(smem_u32(&Bs[st][lrow][lck + 8]), Bn + 8);
            CP_COMMIT();
            CP_WAIT2();
        } else if (c + 1 < NCH) {
            CP_WAIT1();
        } else {
            CP_WAIT0();
        }
        __syncthreads();   // single barrier: data visible + prev readers done
        const int b = c & 3;

        #pragma unroll
        for (int kk = 0; kk < KCH; kk += 16) {
            uint32_t a[2][4];
            #pragma unroll
            for (int mt = 0; mt < 2; mt++)
                ldsm_x4(a[mt][0], a[mt][1], a[mt][2], a[mt][3],
                        smem_u32(&As[b][wm * 32 + mt * 16 + lrow16][kk + chalf]));
            #pragma unroll
            for (int g = 0; g < 4; g++) {
                uint32_t r0, r1, r2, r3;
                ldsm_x4(r0, r1, r2, r3,
                        smem_u32(&Bs[b][wn * 64 + g * 16 + lrow16][kk + chalf]));
                mma16816h(acc[0][2 * g],     a[0], r0, r2);
                mma16816h(acc[1][2 * g],     a[1], r0, r2);
                mma16816h(acc[0][2 * g + 1], a[0], r1, r3);
                mma16816h(acc[1][2 * g + 1], a[1], r1, r3);
            }
        }
    }

    // ---- epilogue: +bias, (q: *log2e/8), fp16, into [B, H, S, 64] scratch ----
    const float s = (z == 0) ? 0.125f * L2E : 1.0f;
    #pragma unroll
    for (int mt = 0; mt < 2; mt++) {
        const int row0 = m0 + wm * 32 + mt * 16 + fr;
        const int b0r = row0 >> 11, s0 = row0 & (SQ - 1);
        const int row1 = row0 + 8;
        const int b1r = row1 >> 11, s1 = row1 & (SQ - 1);
        #pragma unroll
        for (int nt = 0; nt < 8; nt++) {
            const int col = n0 + wn * 64 + nt * 8 + fc;
            const int h = col >> 6, dd = col & 63;
            const float bz0 = bias[col], bz1 = bias[col + 1];
            __half* p0 = dst + ((size_t)(b0r * NH + h) * SQ + s0) * HD + dd;
            __half* p1 = dst + ((size_t)(b1r * NH + h) * SQ + s1) * HD + dd;
            *(__half2*)p0 = __floats2half2_rn((acc[mt][nt][0] + bz0) * s,
                                              (acc[mt][nt][1] + bz1) * s);
            *(__half2*)p1 = __floats2half2_rn((acc[mt][nt][2] + bz0) * s,
                                              (acc[mt][nt][3] + bz1) * s);
        }
    }
}

// ============================================================================
// Flash attention: fp16 scratch, 4-stage cp.async ring, one barrier/tile.
// exp2-domain softmax; S accumulators INITIALIZED with mask*log2e (MMA adds
// QK on top — same sum, no post-MMA mask pass). P computed with packed
// ex2.approx.f16x2 (half the MUFU ops; output IS the fp16 fragment).
// Row-sum l on the tensor pipe (ones-column MMA).
// ============================================================================
#define BQ 128
#define BK 64
#define VP 72
#define FST 4
#define FA_SMEM (FST * 2 * BK * VP * 2)   // 73728 B

__global__ __launch_bounds__(256, 2) void flash_attn_mma(
    const float* __restrict__ mask, float* __restrict__ out)
{
    extern __shared__ __align__(16) char smraw[];
    __half (*KVs)[2][BK][VP] = (__half (*)[2][BK][VP])smraw;

    const int tid = threadIdx.x;
    const int wid = tid >> 5, lane = tid & 31;
    const int fr = lane >> 2, fc = (lane & 3) * 2;
    const int bh = blockIdx.y;
    const int b = bh >> 4, h = bh & 15;
    const int q0 = blockIdx.x * BQ;
    const int qrow = q0 + wid * 16;

    const __half* Qg = g_qh + (size_t)bh * SQ * HD;
    const __half* Kg = g_kh + (size_t)bh * SQ * HD;
    const __half* Vg = g_vh + (size_t)bh * SQ * HD;
    const float* mrow = mask + (size_t)b * SQ;

    // ---- Q fragments: raw 32-bit loads from fp16 scratch (already scaled) ----
    uint32_t qf[4][4];
    #pragma unroll
    for (int kc = 0; kc < 4; kc++) {
        #pragma unroll
        for (int rr = 0; rr < 2; rr++) {
            const __half* p = Qg + (size_t)(qrow + fr + rr * 8) * HD + kc * 16 + fc;
            qf[kc][rr]     = *(const uint32_t*)p;
            qf[kc][rr + 2] = *(const uint32_t*)(p + 8);
        }
    }

    float accO[8][4];
    #pragma unroll
    for (int j = 0; j < 8; j++)
        #pragma unroll
        for (int i = 0; i < 4; i++) accO[j][i] = 0.f;
    float accL[4] = { 0.f, 0.f, 0.f, 0.f };   // l via ones-column MMA
    float m0r = -1e30f, m1r = -1e30f;
    const uint32_t ONE2 = 0x3C003C00u;        // half2(1.0, 1.0)

    // cp.async mapping: 64 rows x 64 halves; 4 threads/row x 2 x 8 halves
    const int krow = tid >> 2;
    const int kcol = (tid & 3) * 16;      // halves

    const int NIT = SQ / BK;   // 32

    // prologue: stage tiles 0 and 1
    #pragma unroll
    for (int p = 0; p < 2; p++) {
        const __half* kp = Kg + (size_t)(p * BK + krow) * HD + kcol;
        const __half* vp = Vg + (size_t)(p * BK + krow) * HD + kcol;
        CP16(smem_u32(&KVs[p][0][krow][kcol]),     kp);
        CP16(smem_u32(&KVs[p][0][krow][kcol + 8]), kp + 8);
        CP16(smem_u32(&KVs[p][1][krow][kcol]),     vp);
        CP16(smem_u32(&KVs[p][1][krow][kcol + 8]), vp + 8);
        CP_COMMIT();
    }

    const int lrow16 = lane & 15;
    const int chalf = (lane & 16) >> 1;

    for (int it = 0; it < NIT; it++) {
        if (it + 2 < NIT) {
            const int st = (it + 2) & 3;
            const __half* kp = Kg + (size_t)((it + 2) * BK + krow) * HD + kcol;
            const __half* vp = Vg + (size_t)((it + 2) * BK + krow) * HD + kcol;
            CP16(smem_u32(&KVs[st][0][krow][kcol]),     kp);
            CP16(smem_u32(&KVs[st][0][krow][kcol + 8]), kp + 8);
            CP16(smem_u32(&KVs[st][1][krow][kcol]),     vp);
            CP16(smem_u32(&KVs[st][1][krow][kcol + 8]), vp + 8);
            CP_COMMIT();
            CP_WAIT2();
        } else if (it + 1 < NIT) {
            CP_WAIT1();
        } else {
            CP_WAIT0();
        }
        __syncthreads();   // single barrier per tile
        const int bf = it & 3;
        const uint32_t kh_b = smem_u32(&KVs[bf][0][0][0]);
        const uint32_t vh_b = smem_u32(&KVs[bf][1][0][0]);
        const int j0 = it * BK;

        // ---- S accumulators start as mask*log2e (MMA accumulates QK on top) ----
        float sacc[8][4];
        #pragma unroll
        for (int j = 0; j < 8; j++) {
            float2 mv = *(const float2*)(mrow + j0 + j * 8 + fc);
            const float mx = mv.x * L2E, my = mv.y * L2E;
            sacc[j][0] = mx; sacc[j][1] = my;
            sacc[j][2] = mx; sacc[j][3] = my;
        }

        // ---- S = mask + Q K^T (log2 domain) ----
        #pragma unroll
        for (int kc = 0; kc < 4; kc++) {
            #pragma unroll
            for (int g = 0; g < 4; g++) {
                uint32_t r0, r1, r2, r3;
                uint32_t addr = kh_b +
                    ((g * 16 + lrow16) * VP + kc * 16 + chalf) * 2;
                ldsm_x4(r0, r1, r2, r3, addr);
                mma16816h(sacc[2 * g],     qf[kc], r0, r2);
                mma16816h(sacc[2 * g + 1], qf[kc], r1, r3);
            }
        }

        // ---- online softmax in exp2 domain ----
        float rmax0 = -1e30f, rmax1 = -1e30f;
        #pragma unroll
        for (int j = 0; j < 8; j++) {
            rmax0 = fmaxf(rmax0, fmaxf(sacc[j][0], sacc[j][1]));
            rmax1 = fmaxf(rmax1, fmaxf(sacc[j][2], sacc[j][3]));
        }
        rmax0 = fmaxf(rmax0, __shfl_xor_sync(0xffffffffu, rmax0, 1));
        rmax0 = fmaxf(rmax0, __shfl_xor_sync(0xffffffffu, rmax0, 2));
        rmax1 = fmaxf(rmax1, __shfl_xor_sync(0xffffffffu, rmax1, 1));
        rmax1 = fmaxf(rmax1, __shfl_xor_sync(0xffffffffu, rmax1, 2));

        const float mn0 = fmaxf(m0r, rmax0);
        const float mn1 = fmaxf(m1r, rmax1);
        const float a0 = ex2(m0r - mn0);
        const float a1 = ex2(m1r - mn1);
        m0r = mn0; m1r = mn1;

        // ---- P = 2^(s-m): pack to half2, one MUFU per PAIR; output = fragment ----
        uint32_t ph[16];
        #pragma unroll
        for (int j = 0; j < 8; j++) {
            uint32_t d0 = h2bits(__floats2half2_rn(sacc[j][0] - mn0,
                                                   sacc[j][1] - mn0));
            uint32_t d1 = h2bits(__floats2half2_rn(sacc[j][2] - mn1,
                                                   sacc[j][3] - mn1));
            ph[2 * j]     = ex2h2(d0);
            ph[2 * j + 1] = ex2h2(d1);
        }
        #pragma unroll
        for (int j = 0; j < 8; j++) {
            accO[j][0] *= a0; accO[j][1] *= a0;
            accO[j][2] *= a1; accO[j][3] *= a1;
        }
        accL[0] *= a0; accL[1] *= a0;
        accL[2] *= a1; accL[3] *= a1;

        // ---- O += P V, plus l += P @ ones (tensor-pipe row sums) ----
        #pragma unroll
        for (int kc = 0; kc < 4; kc++) {
            uint32_t pah[4] = { ph[4*kc], ph[4*kc+1], ph[4*kc+2], ph[4*kc+3] };
            mma16816h(accL, pah, ONE2, ONE2);
            #pragma unroll
            for (int dg = 0; dg < 4; dg++) {
                uint32_t off = vh_b + ((kc * 16 + lrow16) * VP + dg * 16 + chalf) * 2;
                uint32_t h0, h1, h2, h3;
                ldsm_x4_t(h0, h1, h2, h3, off);
                mma16816h(accO[2 * dg],     pah, h0, h1);
                mma16816h(accO[2 * dg + 1], pah, h2, h3);
            }
        }
    }

    // ---- epilogue: l is already complete per row (MMA summed over k) ----
    const float inv0 = 1.0f / accL[0], inv1 = 1.0f / accL[2];

    const int s0 = qrow + fr, s1 = s0 + 8;
    float* o0 = out + ((size_t)b * SQ + s0) * DM + h * HD;
    float* o1 = out + ((size_t)b * SQ + s1) * DM + h * HD;
    #pragma unroll
    for (int dt = 0; dt < 8; dt++) {
        const int d = dt * 8 + fc;
        *(float2*)(o0 + d) = make_float2(accO[dt][0] * inv0, accO[dt][1] * inv0);
        *(float2*)(o1 + d) = make_float2(accO[dt][2] * inv1, accO[dt][3] * inv1);
    }
}

extern "C" void kernel_launch(void* const* d_in, const int* in_sizes, int n_in,
                              void* d_out, int out_size)
{
    const float* X   = (const float*)d_in[0];
    const float* Mk  = (const float*)d_in[1];
    const float* Wq  = (const float*)d_in[2];
    const float* bq  = (const float*)d_in[3];
    const float* Wk  = (const float*)d_in[4];
    const float* bk  = (const float*)d_in[5];
    const float* Wv  = (const float*)d_in[6];
    const float* bv  = (const float*)d_in[7];
    float* out = (float*)d_out;

    cudaFuncSetAttribute(qkv_gemm_f16,
                         cudaFuncAttributeMaxDynamicSharedMemorySize, QKV_SMEM);
    cudaFuncSetAttribute(flash_attn_mma,
                         cudaFuncAttributeMaxDynamicSharedMemorySize, FA_SMEM);

    cvt_x<<<NB * SQ * DM / 2048, 256>>>(X, NB * SQ * DM);
    cvt_w<<<3 * DM * DM / 2048, 256>>>(Wq, Wk, Wv);
    qkv_gemm_f16<<<dim3(8, 64, 3), 256, QKV_SMEM>>>(bq, bk, bv);
    flash_attn_mma<<<dim3(SQ / BQ, NB * NH), 256, FA_SMEM>>>(Mk, out);
}